// round 3
// baseline (speedup 1.0000x reference)
#include <cuda_runtime.h>
#include <cuda_bf16.h>
#include <cstdint>

#define NODES_MAX 100000
#define DIM 128

// Scratch (allocation-free rule: __device__ globals)
__device__ float g_h[(size_t)NODES_MAX * DIM];     // relu(x@W0^T+b0)
__device__ float g_agg[(size_t)NODES_MAX * DIM];   // scatter-add accumulator
__device__ float g_deg[NODES_MAX];                 // degree accumulator

// ---------------------------------------------------------------------------
// GEMM0: h = relu(A @ W^T + bias), A:[n,128] row-major, W:[128,128] row-major
// Tile: 64 rows x 128 cols, BK=16. 256 threads, each computes 4x8.
// ---------------------------------------------------------------------------
__global__ __launch_bounds__(256) void gemm0_kernel(
    const float* __restrict__ A, const float* __restrict__ W,
    const float* __restrict__ bias, float* __restrict__ C, int n)
{
    __shared__ __align__(16) float As[64 * 20];   // padded ld=20: conflict-free
    __shared__ __align__(16) float Bs[16 * 128];  // [k][n]
    __shared__ float biasS[128];

    const int tid = threadIdx.x;
    const int R0  = blockIdx.x * 64;
    if (tid < 128) biasS[tid] = bias[tid];

    const int lrow  = tid >> 2;    // 0..63 (A tile row to load)
    const int lq    = tid & 3;     // float4 slot within BK=16
    const int wn    = tid & 127;   // W row (output col) to load
    const int wq0   = tid >> 7;    // 0..1
    const int row_g = tid >> 4;    // 0..15
    const int col_g = tid & 15;    // 0..15

    float acc[4][8];
#pragma unroll
    for (int i = 0; i < 4; i++)
#pragma unroll
        for (int j = 0; j < 8; j++) acc[i][j] = 0.f;

    const int  grow    = R0 + lrow;
    const bool arow_ok = (grow < n);

    for (int kb = 0; kb < 8; kb++) {
        const int k0 = kb * 16;
        float4 av = make_float4(0.f, 0.f, 0.f, 0.f);
        if (arow_ok)
            av = *(const float4*)(A + (size_t)grow * DIM + k0 + lq * 4);
        float4 wv0 = *(const float4*)(W + wn * DIM + k0 + wq0 * 4);
        float4 wv1 = *(const float4*)(W + wn * DIM + k0 + (wq0 + 2) * 4);

        __syncthreads();  // previous iter's smem reads done
        *(float4*)(As + lrow * 20 + lq * 4) = av;
        {
            int q = wq0;
            Bs[(q * 4 + 0) * 128 + wn] = wv0.x;
            Bs[(q * 4 + 1) * 128 + wn] = wv0.y;
            Bs[(q * 4 + 2) * 128 + wn] = wv0.z;
            Bs[(q * 4 + 3) * 128 + wn] = wv0.w;
            q = wq0 + 2;
            Bs[(q * 4 + 0) * 128 + wn] = wv1.x;
            Bs[(q * 4 + 1) * 128 + wn] = wv1.y;
            Bs[(q * 4 + 2) * 128 + wn] = wv1.z;
            Bs[(q * 4 + 3) * 128 + wn] = wv1.w;
        }
        __syncthreads();

#pragma unroll
        for (int kk = 0; kk < 16; kk++) {
            float a[4];
#pragma unroll
            for (int i = 0; i < 4; i++) a[i] = As[(row_g * 4 + i) * 20 + kk];
            float4 b0 = *(const float4*)(Bs + kk * 128 + col_g * 8);
            float4 b1 = *(const float4*)(Bs + kk * 128 + col_g * 8 + 4);
            float b[8] = {b0.x, b0.y, b0.z, b0.w, b1.x, b1.y, b1.z, b1.w};
#pragma unroll
            for (int i = 0; i < 4; i++)
#pragma unroll
                for (int j = 0; j < 8; j++)
                    acc[i][j] = fmaf(a[i], b[j], acc[i][j]);
        }
    }

#pragma unroll
    for (int i = 0; i < 4; i++) {
        int r = R0 + row_g * 4 + i;
        if (r < n) {
            float o[8];
#pragma unroll
            for (int j = 0; j < 8; j++) {
                float v = acc[i][j] + biasS[col_g * 8 + j];
                o[j] = v > 0.f ? v : 0.f;
            }
            float4* dst = (float4*)(C + (size_t)r * DIM + col_g * 8);
            dst[0] = make_float4(o[0], o[1], o[2], o[3]);
            dst[1] = make_float4(o[4], o[5], o[6], o[7]);
        }
    }
}

// ---------------------------------------------------------------------------
// Scatter: one warp per edge. agg[row] += h[col] (vectorized RED), deg[row]+=1
// ---------------------------------------------------------------------------
__global__ __launch_bounds__(256) void scatter_kernel(
    const int* __restrict__ ei, int n_edges)
{
    int e    = blockIdx.x * 8 + (threadIdx.x >> 5);
    int lane = threadIdx.x & 31;
    if (e >= n_edges) return;
    int r = ei[e];
    int c = ei[n_edges + e];

    const float4 v = *(const float4*)(g_h + (size_t)c * DIM + lane * 4);
    float* dst = g_agg + (size_t)r * DIM + lane * 4;
    asm volatile("red.global.add.v4.f32 [%0], {%1,%2,%3,%4};"
                 :: "l"(dst), "f"(v.x), "f"(v.y), "f"(v.z), "f"(v.w)
                 : "memory");
    if (lane == 0)
        asm volatile("red.global.add.f32 [%0], %1;"
                     :: "l"(g_deg + r), "f"(1.0f) : "memory");
}

// ---------------------------------------------------------------------------
// Fused: a = h + agg/max(deg,1);  h2 = relu(a@W1^T+b1);  out = h2@Wc^T+bc
// Same GEMM tile as gemm0; classifier epilogue over h2 tile staged in smem.
// ---------------------------------------------------------------------------
__global__ __launch_bounds__(256) void gemm1_cls_kernel(
    const float* __restrict__ W1, const float* __restrict__ b1,
    const float* __restrict__ Wc, const float* __restrict__ bc,
    float* __restrict__ out, int n)
{
    // manual layout: WcS[4*132] | bcS[4] | biasS[128] | (As[64*20] Bs[16*128])
    //                                                    aliased later by Cs[64*132]
    __shared__ __align__(16) float sm[660 + 64 * 132];
    float* WcS   = sm;          // 528 floats
    float* bcS   = sm + 528;    // 4
    float* biasS = sm + 532;    // 128
    float* As    = sm + 660;    // 1280
    float* Bs    = sm + 660 + 1280; // 2048
    float* Cs    = sm + 660;    // 8448, aliases As/Bs

    const int tid = threadIdx.x;
    const int R0  = blockIdx.x * 64;

    // stage classifier weights + bias
    {
        int i0 = tid, i1 = tid + 256;
        WcS[(i0 >> 7) * 132 + (i0 & 127)] = Wc[i0];
        WcS[(i1 >> 7) * 132 + (i1 & 127)] = Wc[i1];
        if (tid < 4)   bcS[tid]   = bc[tid];
        if (tid < 128) biasS[tid] = b1[tid];
    }

    const int lrow  = tid >> 2;
    const int lq    = tid & 3;
    const int wn    = tid & 127;
    const int wq0   = tid >> 7;
    const int row_g = tid >> 4;
    const int col_g = tid & 15;

    const int  grow    = R0 + lrow;
    const bool arow_ok = (grow < n);
    float invd = 0.f;
    if (arow_ok) invd = 1.0f / fmaxf(g_deg[grow], 1.0f);

    float acc[4][8];
#pragma unroll
    for (int i = 0; i < 4; i++)
#pragma unroll
        for (int j = 0; j < 8; j++) acc[i][j] = 0.f;

    for (int kb = 0; kb < 8; kb++) {
        const int k0 = kb * 16;
        float4 av = make_float4(0.f, 0.f, 0.f, 0.f);
        if (arow_ok) {
            float4 hv = *(const float4*)(g_h   + (size_t)grow * DIM + k0 + lq * 4);
            float4 gv = *(const float4*)(g_agg + (size_t)grow * DIM + k0 + lq * 4);
            av = make_float4(fmaf(gv.x, invd, hv.x), fmaf(gv.y, invd, hv.y),
                             fmaf(gv.z, invd, hv.z), fmaf(gv.w, invd, hv.w));
        }
        float4 wv0 = *(const float4*)(W1 + wn * DIM + k0 + wq0 * 4);
        float4 wv1 = *(const float4*)(W1 + wn * DIM + k0 + (wq0 + 2) * 4);

        __syncthreads();
        *(float4*)(As + lrow * 20 + lq * 4) = av;
        {
            int q = wq0;
            Bs[(q * 4 + 0) * 128 + wn] = wv0.x;
            Bs[(q * 4 + 1) * 128 + wn] = wv0.y;
            Bs[(q * 4 + 2) * 128 + wn] = wv0.z;
            Bs[(q * 4 + 3) * 128 + wn] = wv0.w;
            q = wq0 + 2;
            Bs[(q * 4 + 0) * 128 + wn] = wv1.x;
            Bs[(q * 4 + 1) * 128 + wn] = wv1.y;
            Bs[(q * 4 + 2) * 128 + wn] = wv1.z;
            Bs[(q * 4 + 3) * 128 + wn] = wv1.w;
        }
        __syncthreads();

#pragma unroll
        for (int kk = 0; kk < 16; kk++) {
            float a[4];
#pragma unroll
            for (int i = 0; i < 4; i++) a[i] = As[(row_g * 4 + i) * 20 + kk];
            float4 b0 = *(const float4*)(Bs + kk * 128 + col_g * 8);
            float4 b1v = *(const float4*)(Bs + kk * 128 + col_g * 8 + 4);
            float b[8] = {b0.x, b0.y, b0.z, b0.w, b1v.x, b1v.y, b1v.z, b1v.w};
#pragma unroll
            for (int i = 0; i < 4; i++)
#pragma unroll
                for (int j = 0; j < 8; j++)
                    acc[i][j] = fmaf(a[i], b[j], acc[i][j]);
        }
    }

    __syncthreads();  // done reading As/Bs; Cs aliases them

    // bias + relu, stage h2 tile into Cs (padded ld=132, conflict-free)
#pragma unroll
    for (int i = 0; i < 4; i++) {
        float o[8];
#pragma unroll
        for (int j = 0; j < 8; j++) {
            float v = acc[i][j] + biasS[col_g * 8 + j];
            o[j] = v > 0.f ? v : 0.f;
        }
        float* dst = Cs + (row_g * 4 + i) * 132 + col_g * 8;
        *(float4*)(dst)     = make_float4(o[0], o[1], o[2], o[3]);
        *(float4*)(dst + 4) = make_float4(o[4], o[5], o[6], o[7]);
    }
    __syncthreads();

    // classifier: thread = (node i, class cc)
    {
        int i  = tid >> 2;   // 0..63
        int cc = tid & 3;    // 0..3
        float s = bcS[cc];
        const float* hrow = Cs + i * 132;
        const float* wrow = WcS + cc * 132;
#pragma unroll
        for (int k4 = 0; k4 < 32; k4++) {
            float4 hv = *(const float4*)(hrow + k4 * 4);
            float4 wv = *(const float4*)(wrow + k4 * 4);
            s = fmaf(hv.x, wv.x, s);
            s = fmaf(hv.y, wv.y, s);
            s = fmaf(hv.z, wv.z, s);
            s = fmaf(hv.w, wv.w, s);
        }
        int r = R0 + i;
        if (r < n) out[(size_t)r * 4 + cc] = s;   // fully coalesced
    }
}

// ---------------------------------------------------------------------------
extern "C" void kernel_launch(void* const* d_in, const int* in_sizes, int n_in,
                              void* d_out, int out_size)
{
    const float* x  = (const float*)d_in[0];
    const int*   ei = (const int*)  d_in[1];
    const float* W0 = (const float*)d_in[2];
    const float* b0 = (const float*)d_in[3];
    const float* W1 = (const float*)d_in[4];
    const float* b1 = (const float*)d_in[5];
    const float* Wc = (const float*)d_in[6];
    const float* bc = (const float*)d_in[7];
    float* out = (float*)d_out;

    const int n       = in_sizes[0] / DIM;
    const int n_edges = in_sizes[1] / 2;

    void *aggp, *degp, *hp;
    cudaGetSymbolAddress(&aggp, g_agg);
    cudaGetSymbolAddress(&degp, g_deg);
    cudaGetSymbolAddress(&hp,   g_h);

    cudaMemsetAsync(aggp, 0, (size_t)n * DIM * sizeof(float));
    cudaMemsetAsync(degp, 0, (size_t)n * sizeof(float));

    const int gblocks = (n + 63) / 64;
    gemm0_kernel<<<gblocks, 256>>>(x, W0, b0, (float*)hp, n);
    scatter_kernel<<<(n_edges + 7) / 8, 256>>>(ei, n_edges);
    gemm1_cls_kernel<<<gblocks, 256>>>(W1, b1, Wc, bc, out, n);
}

// round 6
// speedup vs baseline: 1.3336x; 1.3336x over previous
#include <cuda_runtime.h>
#include <cuda_bf16.h>
#include <cstdint>

#define NODES_MAX 100000
#define DIM 128

typedef unsigned long long ull;

// Scratch (allocation-free rule: __device__ globals)
__device__ float g_h[(size_t)NODES_MAX * DIM];     // relu(x@W0^T+b0)
__device__ float g_agg[(size_t)NODES_MAX * DIM];   // scatter-add accumulator
__device__ float g_deg[NODES_MAX];                 // degree accumulator

__device__ __forceinline__ ull pack2(float a, float b) {
    ull r;
    asm("mov.b64 %0, {%1, %2};" : "=l"(r) : "f"(a), "f"(b));
    return r;
}
__device__ __forceinline__ void unpack2(float& lo, float& hi, ull v) {
    asm("mov.b64 {%0, %1}, %2;" : "=f"(lo), "=f"(hi) : "l"(v));
}
__device__ __forceinline__ ull ffma2(ull a, ull b, ull c) {
    ull d;
    asm("fma.rn.f32x2 %0, %1, %2, %3;" : "=l"(d) : "l"(a), "l"(b), "l"(c));
    return d;
}

// ---------------------------------------------------------------------------
// GEMM0: h = relu(A @ W^T + b), A:[n,128], W:[128,128] row-major.
// Block tile 128x128, BK=16, 256 threads, 8x8 per thread via f32x2 FFMA2.
// As stored transposed [k][m]; Bs stored [k][n].
// ---------------------------------------------------------------------------
__global__ __launch_bounds__(256, 2) void gemm0_kernel(
    const float* __restrict__ A, const float* __restrict__ W,
    const float* __restrict__ bias, float* __restrict__ C, int n)
{
    __shared__ __align__(16) float As[16 * 128];
    __shared__ __align__(16) float Bs[16 * 128];
    __shared__ float biasS[128];

    const int tid = threadIdx.x;
    const int R0  = blockIdx.x * 128;
    if (tid < 128) biasS[tid] = bias[tid];

    const int lm = tid >> 1;       // 0..127: A row / W row this thread stages
    const int lq = tid & 1;        // which 8-k half of BK
    const int row_g = tid >> 4;    // 0..15  -> m0 = row_g*8
    const int col_g = tid & 15;    // 0..15  -> n0 = col_g*8
    const int m0 = row_g * 8;
    const int n0 = col_g * 8;

    ull acc[8][4];
#pragma unroll
    for (int i = 0; i < 8; i++)
#pragma unroll
        for (int q = 0; q < 4; q++) acc[i][q] = 0ull;

    const int  grow    = R0 + lm;
    const bool arow_ok = (grow < n);

    for (int kb = 0; kb < 8; kb++) {
        const int k0 = kb * 16;
        float4 av0 = make_float4(0.f, 0.f, 0.f, 0.f), av1 = av0;
        if (arow_ok) {
            av0 = *(const float4*)(A + (size_t)grow * DIM + k0 + lq * 8);
            av1 = *(const float4*)(A + (size_t)grow * DIM + k0 + lq * 8 + 4);
        }
        float4 wv0 = *(const float4*)(W + lm * DIM + k0 + lq * 8);
        float4 wv1 = *(const float4*)(W + lm * DIM + k0 + lq * 8 + 4);

        __syncthreads();  // prior iter's smem reads done
        {
            const int kb8 = lq * 8;
            As[(kb8 + 0) * 128 + lm] = av0.x;
            As[(kb8 + 1) * 128 + lm] = av0.y;
            As[(kb8 + 2) * 128 + lm] = av0.z;
            As[(kb8 + 3) * 128 + lm] = av0.w;
            As[(kb8 + 4) * 128 + lm] = av1.x;
            As[(kb8 + 5) * 128 + lm] = av1.y;
            As[(kb8 + 6) * 128 + lm] = av1.z;
            As[(kb8 + 7) * 128 + lm] = av1.w;
            Bs[(kb8 + 0) * 128 + lm] = wv0.x;
            Bs[(kb8 + 1) * 128 + lm] = wv0.y;
            Bs[(kb8 + 2) * 128 + lm] = wv0.z;
            Bs[(kb8 + 3) * 128 + lm] = wv0.w;
            Bs[(kb8 + 4) * 128 + lm] = wv1.x;
            Bs[(kb8 + 5) * 128 + lm] = wv1.y;
            Bs[(kb8 + 6) * 128 + lm] = wv1.z;
            Bs[(kb8 + 7) * 128 + lm] = wv1.w;
        }
        __syncthreads();

#pragma unroll
        for (int kk = 0; kk < 16; kk++) {
            float4 a0 = *(const float4*)(As + kk * 128 + m0);
            float4 a1 = *(const float4*)(As + kk * 128 + m0 + 4);
            ulonglong2 bA = *(const ulonglong2*)(Bs + kk * 128 + n0);
            ulonglong2 bB = *(const ulonglong2*)(Bs + kk * 128 + n0 + 4);
            ull b[4] = {bA.x, bA.y, bB.x, bB.y};
            float af[8] = {a0.x, a0.y, a0.z, a0.w, a1.x, a1.y, a1.z, a1.w};
#pragma unroll
            for (int i = 0; i < 8; i++) {
                ull a2 = pack2(af[i], af[i]);
#pragma unroll
                for (int q = 0; q < 4; q++)
                    acc[i][q] = ffma2(a2, b[q], acc[i][q]);
            }
        }
    }

    // epilogue: bias + relu -> C
#pragma unroll
    for (int i = 0; i < 8; i++) {
        int r = R0 + m0 + i;
        if (r < n) {
            float o[8];
#pragma unroll
            for (int q = 0; q < 4; q++) unpack2(o[2*q], o[2*q+1], acc[i][q]);
#pragma unroll
            for (int j = 0; j < 8; j++) {
                float v = o[j] + biasS[n0 + j];
                o[j] = v > 0.f ? v : 0.f;
            }
            float4* dst = (float4*)(C + (size_t)r * DIM + n0);
            dst[0] = make_float4(o[0], o[1], o[2], o[3]);
            dst[1] = make_float4(o[4], o[5], o[6], o[7]);
        }
    }
}

// ---------------------------------------------------------------------------
// Scatter: one warp per edge. agg[row] += h[col] (vectorized RED), deg[row]+=1
// ---------------------------------------------------------------------------
__global__ __launch_bounds__(256) void scatter_kernel(
    const int* __restrict__ ei, int n_edges)
{
    int e    = blockIdx.x * 8 + (threadIdx.x >> 5);
    int lane = threadIdx.x & 31;
    if (e >= n_edges) return;
    int r = ei[e];
    int c = ei[n_edges + e];

    const float4 v = *(const float4*)(g_h + (size_t)c * DIM + lane * 4);
    float* dst = g_agg + (size_t)r * DIM + lane * 4;
    asm volatile("red.global.add.v4.f32 [%0], {%1,%2,%3,%4};"
                 :: "l"(dst), "f"(v.x), "f"(v.y), "f"(v.z), "f"(v.w)
                 : "memory");
    if (lane == 0)
        asm volatile("red.global.add.f32 [%0], %1;"
                     :: "l"(g_deg + r), "f"(1.0f) : "memory");
}

// ---------------------------------------------------------------------------
// Fused: a = h + agg/max(deg,1); h2 = relu(a@W1^T+b1); out = h2@Wc^T+bc
// Same 128x128 FFMA2 tile; classifier folded into a register epilogue with
// a 16-lane shfl reduction (no smem staging of h2).
// ---------------------------------------------------------------------------
__global__ __launch_bounds__(256, 2) void gemm1_cls_kernel(
    const float* __restrict__ W1, const float* __restrict__ b1,
    const float* __restrict__ Wc, const float* __restrict__ bc,
    float* __restrict__ out, int n)
{
    __shared__ __align__(16) float As[16 * 128];
    __shared__ __align__(16) float Bs[16 * 128];
    __shared__ float biasS[128];
    __shared__ float WcS[4 * 128];
    __shared__ float bcS[4];

    const int tid = threadIdx.x;
    const int R0  = blockIdx.x * 128;
    if (tid < 128) biasS[tid] = b1[tid];
    WcS[tid]       = Wc[tid];
    WcS[tid + 256] = Wc[tid + 256];
    if (tid < 4) bcS[tid] = bc[tid];

    const int lm = tid >> 1;
    const int lq = tid & 1;
    const int row_g = tid >> 4;
    const int col_g = tid & 15;
    const int m0 = row_g * 8;
    const int n0 = col_g * 8;

    ull acc[8][4];
#pragma unroll
    for (int i = 0; i < 8; i++)
#pragma unroll
        for (int q = 0; q < 4; q++) acc[i][q] = 0ull;

    const int  grow    = R0 + lm;
    const bool arow_ok = (grow < n);
    float invd = 0.f;
    if (arow_ok) invd = 1.0f / fmaxf(g_deg[grow], 1.0f);

    for (int kb = 0; kb < 8; kb++) {
        const int k0 = kb * 16;
        float av[8] = {0.f, 0.f, 0.f, 0.f, 0.f, 0.f, 0.f, 0.f};
        if (arow_ok) {
            float4 h0 = *(const float4*)(g_h   + (size_t)grow * DIM + k0 + lq * 8);
            float4 h1 = *(const float4*)(g_h   + (size_t)grow * DIM + k0 + lq * 8 + 4);
            float4 g0 = *(const float4*)(g_agg + (size_t)grow * DIM + k0 + lq * 8);
            float4 g1 = *(const float4*)(g_agg + (size_t)grow * DIM + k0 + lq * 8 + 4);
            av[0] = fmaf(g0.x, invd, h0.x); av[1] = fmaf(g0.y, invd, h0.y);
            av[2] = fmaf(g0.z, invd, h0.z); av[3] = fmaf(g0.w, invd, h0.w);
            av[4] = fmaf(g1.x, invd, h1.x); av[5] = fmaf(g1.y, invd, h1.y);
            av[6] = fmaf(g1.z, invd, h1.z); av[7] = fmaf(g1.w, invd, h1.w);
        }
        float4 wv0 = *(const float4*)(W1 + lm * DIM + k0 + lq * 8);
        float4 wv1 = *(const float4*)(W1 + lm * DIM + k0 + lq * 8 + 4);

        __syncthreads();
        {
            const int kb8 = lq * 8;
#pragma unroll
            for (int j = 0; j < 8; j++) As[(kb8 + j) * 128 + lm] = av[j];
            Bs[(kb8 + 0) * 128 + lm] = wv0.x;
            Bs[(kb8 + 1) * 128 + lm] = wv0.y;
            Bs[(kb8 + 2) * 128 + lm] = wv0.z;
            Bs[(kb8 + 3) * 128 + lm] = wv0.w;
            Bs[(kb8 + 4) * 128 + lm] = wv1.x;
            Bs[(kb8 + 5) * 128 + lm] = wv1.y;
            Bs[(kb8 + 6) * 128 + lm] = wv1.z;
            Bs[(kb8 + 7) * 128 + lm] = wv1.w;
        }
        __syncthreads();

#pragma unroll
        for (int kk = 0; kk < 16; kk++) {
            float4 a0 = *(const float4*)(As + kk * 128 + m0);
            float4 a1 = *(const float4*)(As + kk * 128 + m0 + 4);
            ulonglong2 bA = *(const ulonglong2*)(Bs + kk * 128 + n0);
            ulonglong2 bB = *(const ulonglong2*)(Bs + kk * 128 + n0 + 4);
            ull b[4] = {bA.x, bA.y, bB.x, bB.y};
            float af[8] = {a0.x, a0.y, a0.z, a0.w, a1.x, a1.y, a1.z, a1.w};
#pragma unroll
            for (int i = 0; i < 8; i++) {
                ull a2 = pack2(af[i], af[i]);
#pragma unroll
                for (int q = 0; q < 4; q++)
                    acc[i][q] = ffma2(a2, b[q], acc[i][q]);
            }
        }
    }

    // epilogue: bias+relu -> partial classifier dot over this thread's 8 cols
    float p[8][4];
#pragma unroll
    for (int i = 0; i < 8; i++) {
        float h2[8];
#pragma unroll
        for (int q = 0; q < 4; q++) unpack2(h2[2*q], h2[2*q+1], acc[i][q]);
#pragma unroll
        for (int j = 0; j < 8; j++) {
            float v = h2[j] + biasS[n0 + j];
            h2[j] = v > 0.f ? v : 0.f;
        }
#pragma unroll
        for (int c = 0; c < 4; c++) {
            float s = 0.f;
#pragma unroll
            for (int j = 0; j < 8; j++)
                s = fmaf(h2[j], WcS[c * 128 + n0 + j], s);
            p[i][c] = s;
        }
    }

    // reduce over the 16 col_g lanes (lanes [0..15] / [16..31] of each warp)
#pragma unroll
    for (int d = 8; d >= 1; d >>= 1)
#pragma unroll
        for (int i = 0; i < 8; i++)
#pragma unroll
            for (int c = 0; c < 4; c++)
                p[i][c] += __shfl_down_sync(0xffffffffu, p[i][c], d, 16);

    if (col_g == 0) {
#pragma unroll
        for (int i = 0; i < 8; i++) {
            int r = R0 + m0 + i;
            if (r < n)
                *(float4*)(out + (size_t)r * 4) =
                    make_float4(p[i][0] + bcS[0], p[i][1] + bcS[1],
                                p[i][2] + bcS[2], p[i][3] + bcS[3]);
        }
    }
}

// ---------------------------------------------------------------------------
extern "C" void kernel_launch(void* const* d_in, const int* in_sizes, int n_in,
                              void* d_out, int out_size)
{
    const float* x  = (const float*)d_in[0];
    const int*   ei = (const int*)  d_in[1];
    const float* W0 = (const float*)d_in[2];
    const float* b0 = (const float*)d_in[3];
    const float* W1 = (const float*)d_in[4];
    const float* b1 = (const float*)d_in[5];
    const float* Wc = (const float*)d_in[6];
    const float* bc = (const float*)d_in[7];
    float* out = (float*)d_out;

    const int n       = in_sizes[0] / DIM;
    const int n_edges = in_sizes[1] / 2;

    void *aggp, *degp, *hp;
    cudaGetSymbolAddress(&aggp, g_agg);
    cudaGetSymbolAddress(&degp, g_deg);
    cudaGetSymbolAddress(&hp,   g_h);

    cudaMemsetAsync(aggp, 0, (size_t)n * DIM * sizeof(float));
    cudaMemsetAsync(degp, 0, (size_t)n * sizeof(float));

    const int gblocks = (n + 127) / 128;
    gemm0_kernel<<<gblocks, 256>>>(x, W0, b0, (float*)hp, n);
    scatter_kernel<<<(n_edges + 7) / 8, 256>>>(ei, n_edges);
    gemm1_cls_kernel<<<gblocks, 256>>>(W1, b1, Wc, bc, out, n);
}

// round 8
// speedup vs baseline: 1.9607x; 1.4701x over previous
#include <cuda_runtime.h>
#include <cuda_bf16.h>
#include <cstdint>

#define NODES_MAX 100000
#define DIM 128

typedef unsigned int u32;

// Scratch (allocation-free rule: __device__ globals)
__device__ float g_h[(size_t)NODES_MAX * DIM];     // relu(x@W0^T+b0)
__device__ float g_agg[(size_t)NODES_MAX * DIM];   // scatter-add accumulator
__device__ float g_deg[NODES_MAX];                 // degree accumulator

// ---------------- smem layout (bytes) ----------------
// header | Ah[64x128 bf16] | Al | Bh[128x128 bf16] | Bl
#define OFF_BIAS 0            // 128 f32
#define OFF_WC   512          // 512 f32
#define OFF_BC   2560         // 4 f32
#define OFF_INVD 2576         // 64 f32
#define OFF_AH   4096         // 16KB
#define OFF_AL   20480        // 16KB
#define OFF_BH   36864        // 32KB
#define OFF_BL   69632        // 32KB
#define SMEM_BYTES 102400

// ---------------- helpers ----------------
__device__ __forceinline__ u32 smem_u32(const void* p) {
    u32 a;
    asm("{ .reg .u64 t; cvta.to.shared.u64 t, %1; cvt.u32.u64 %0, t; }" : "=r"(a) : "l"(p));
    return a;
}

__device__ __forceinline__ void ldsm_x4(u32* r, u32 addr) {
    asm volatile("ldmatrix.sync.aligned.m8n8.x4.shared.b16 {%0,%1,%2,%3}, [%4];"
                 : "=r"(r[0]), "=r"(r[1]), "=r"(r[2]), "=r"(r[3]) : "r"(addr));
}

__device__ __forceinline__ void mma_bf16(float* d, const u32* a, u32 b0, u32 b1) {
    asm volatile(
        "mma.sync.aligned.m16n8k16.row.col.f32.bf16.bf16.f32 "
        "{%0,%1,%2,%3}, {%4,%5,%6,%7}, {%8,%9}, {%0,%1,%2,%3};"
        : "+f"(d[0]), "+f"(d[1]), "+f"(d[2]), "+f"(d[3])
        : "r"(a[0]), "r"(a[1]), "r"(a[2]), "r"(a[3]), "r"(b0), "r"(b1));
}

// byte offset of 16B chunk (row, c8=col*8start) in a 256B-pitch tile with
// XOR-8 chunk swizzle (conflict-free for ldmatrix and staging STS.128)
__device__ __forceinline__ u32 tile_off(int row, int c8) {
    return (u32)(row * 256 + (((c8 >> 3) ^ (row & 7)) << 4));
}

// hi/lo bf16 split of 8 floats -> one 16B store into each of two tiles
__device__ __forceinline__ void split_store(char* smb, int hi_off, int lo_off,
                                            u32 sw, const float* v) {
    u32 h[4], l[4];
#pragma unroll
    for (int j = 0; j < 4; j++) {
        float2 f = make_float2(v[2*j], v[2*j+1]);
        __nv_bfloat162 hb = __float22bfloat162_rn(f);
        float2 hf = __bfloat1622float2(hb);
        float2 r = make_float2(f.x - hf.x, f.y - hf.y);
        __nv_bfloat162 lb = __float22bfloat162_rn(r);
        h[j] = *(u32*)&hb;
        l[j] = *(u32*)&lb;
    }
    *(uint4*)(smb + hi_off + sw) = make_uint4(h[0], h[1], h[2], h[3]);
    *(uint4*)(smb + lo_off + sw) = make_uint4(l[0], l[1], l[2], l[3]);
}

// mainloop shared by both GEMMs: warp tile 16(m) x 128(n), K=128 in smem
__device__ __forceinline__ void mma_mainloop(float acc[16][4], u32 sb,
                                             int wid, int lane) {
    const int m0     = wid * 16;
    const int a_row  = m0 + (lane & 15);
    const int a_sel  = lane >> 4;
    const int b_rowl = (lane & 7) + ((lane >> 4) << 3);
    const int b_sel  = (lane >> 3) & 1;
    const u32 a_hi = sb + OFF_AH + a_row * 256;
    const u32 a_lo = sb + OFF_AL + a_row * 256;
    const u32 b_hi = sb + OFF_BH + b_rowl * 256;
    const u32 b_lo = sb + OFF_BL + b_rowl * 256;

    u32 aH[4], aL[4], bH[4], bL[4];
#pragma unroll
    for (int kk = 0; kk < 8; kk++) {
        const u32 ao = (u32)(((2 * kk + a_sel) ^ (a_row & 7)) << 4);
        ldsm_x4(aH, a_hi + ao);
        ldsm_x4(aL, a_lo + ao);
        const u32 bo = (u32)(((2 * kk + b_sel) ^ (b_rowl & 7)) << 4);
        u32 bha = b_hi + bo, bla = b_lo + bo;
#pragma unroll
        for (int nt = 0; nt < 8; nt++) {
            ldsm_x4(bH, bha);
            ldsm_x4(bL, bla);
            mma_bf16(acc[2*nt],   aH, bH[0], bH[1]);
            mma_bf16(acc[2*nt+1], aH, bH[2], bH[3]);
            mma_bf16(acc[2*nt],   aH, bL[0], bL[1]);
            mma_bf16(acc[2*nt+1], aH, bL[2], bL[3]);
            mma_bf16(acc[2*nt],   aL, bH[0], bH[1]);
            mma_bf16(acc[2*nt+1], aL, bH[2], bH[3]);
            bha += 4096; bla += 4096;   // next 16-n group (16 rows * 256B)
        }
    }
}

// ---------------------------------------------------------------------------
// GEMM0: h = relu(x @ W0^T + b0). CTA: 64 rows, 128 threads.
// ---------------------------------------------------------------------------
__global__ __launch_bounds__(128, 2) void gemm0_mma(
    const float* __restrict__ A, const float* __restrict__ W,
    const float* __restrict__ bias, float* __restrict__ C, int n)
{
    extern __shared__ char sm[];
    const u32 sb = smem_u32(sm);
    const int tid = threadIdx.x, wid = tid >> 5, lane = tid & 31;
    const int R0 = blockIdx.x * 64;

    ((float*)(sm + OFF_BIAS))[tid] = bias[tid];

    // stage A (64x128, split bf16)
#pragma unroll
    for (int s = 0; s < 8; s++) {
        const int chunk = tid + s * 128;
        const int row = chunk >> 4, c8 = (chunk & 15) << 3;
        const u32 sw = tile_off(row, c8);
        float v[8];
        const int gr = R0 + row;
        if (gr < n) {
            float4 a0 = *(const float4*)(A + (size_t)gr * DIM + c8);
            float4 a1 = *(const float4*)(A + (size_t)gr * DIM + c8 + 4);
            v[0]=a0.x; v[1]=a0.y; v[2]=a0.z; v[3]=a0.w;
            v[4]=a1.x; v[5]=a1.y; v[6]=a1.z; v[7]=a1.w;
        } else {
#pragma unroll
            for (int j = 0; j < 8; j++) v[j] = 0.f;
        }
        split_store(sm, OFF_AH, OFF_AL, sw, v);
    }
    // stage B = W0 (128x128, split bf16)
#pragma unroll
    for (int s = 0; s < 16; s++) {
        const int chunk = tid + s * 128;
        const int row = chunk >> 4, c8 = (chunk & 15) << 3;
        const u32 sw = tile_off(row, c8);
        float w[8];
        float4 w0 = *(const float4*)(W + row * DIM + c8);
        float4 w1 = *(const float4*)(W + row * DIM + c8 + 4);
        w[0]=w0.x; w[1]=w0.y; w[2]=w0.z; w[3]=w0.w;
        w[4]=w1.x; w[5]=w1.y; w[6]=w1.z; w[7]=w1.w;
        split_store(sm, OFF_BH, OFF_BL, sw, w);
    }
    __syncthreads();

    float acc[16][4];
#pragma unroll
    for (int j = 0; j < 16; j++)
#pragma unroll
        for (int q = 0; q < 4; q++) acc[j][q] = 0.f;

    mma_mainloop(acc, sb, wid, lane);

    // epilogue: bias + relu -> C
    const int r0 = R0 + wid * 16 + (lane >> 2), r1 = r0 + 8;
    const float* bp = (const float*)(sm + OFF_BIAS);
#pragma unroll
    for (int j = 0; j < 16; j++) {
        const int col = j * 8 + (lane & 3) * 2;
        const float2 bb = *(const float2*)(bp + col);
        if (r0 < n) {
            float2 o = make_float2(fmaxf(acc[j][0] + bb.x, 0.f),
                                   fmaxf(acc[j][1] + bb.y, 0.f));
            *(float2*)(C + (size_t)r0 * DIM + col) = o;
        }
        if (r1 < n) {
            float2 o = make_float2(fmaxf(acc[j][2] + bb.x, 0.f),
                                   fmaxf(acc[j][3] + bb.y, 0.f));
            *(float2*)(C + (size_t)r1 * DIM + col) = o;
        }
    }
}

// ---------------------------------------------------------------------------
// Scatter: one warp per edge. agg[row] += h[col] (vectorized RED), deg[row]+=1
// ---------------------------------------------------------------------------
__global__ __launch_bounds__(256) void scatter_kernel(
    const int* __restrict__ ei, int n_edges)
{
    int e    = blockIdx.x * 8 + (threadIdx.x >> 5);
    int lane = threadIdx.x & 31;
    if (e >= n_edges) return;
    int r = ei[e];
    int c = ei[n_edges + e];

    const float4 v = *(const float4*)(g_h + (size_t)c * DIM + lane * 4);
    float* dst = g_agg + (size_t)r * DIM + lane * 4;
    asm volatile("red.global.add.v4.f32 [%0], {%1,%2,%3,%4};"
                 :: "l"(dst), "f"(v.x), "f"(v.y), "f"(v.z), "f"(v.w)
                 : "memory");
    if (lane == 0)
        asm volatile("red.global.add.f32 [%0], %1;"
                     :: "l"(g_deg + r), "f"(1.0f) : "memory");
}

// ---------------------------------------------------------------------------
// GEMM1 + classifier: a = h + agg/max(deg,1); h2 = relu(a@W1^T+b1);
// out = h2@Wc^T+bc (classifier in register epilogue, 4-lane shfl reduce).
// ---------------------------------------------------------------------------
__global__ __launch_bounds__(128, 2) void gemm1_mma(
    const float* __restrict__ W1, const float* __restrict__ b1,
    const float* __restrict__ Wc, const float* __restrict__ bc,
    float* __restrict__ out, int n)
{
    extern __shared__ char sm[];
    const u32 sb = smem_u32(sm);
    const int tid = threadIdx.x, wid = tid >> 5, lane = tid & 31;
    const int R0 = blockIdx.x * 64;

    ((float*)(sm + OFF_BIAS))[tid] = b1[tid];
    ((float*)(sm + OFF_WC))[tid]       = Wc[tid];
    ((float*)(sm + OFF_WC))[tid + 128] = Wc[tid + 128];
    ((float*)(sm + OFF_WC))[tid + 256] = Wc[tid + 256];
    ((float*)(sm + OFF_WC))[tid + 384] = Wc[tid + 384];
    if (tid < 4) ((float*)(sm + OFF_BC))[tid] = bc[tid];
    if (tid < 64) {
        const int r = R0 + tid;
        ((float*)(sm + OFF_INVD))[tid] =
            (r < n) ? (1.0f / fmaxf(g_deg[r], 1.0f)) : 0.f;
    }
    __syncthreads();   // invd visible before A staging reads it
    const float* invd_s = (const float*)(sm + OFF_INVD);

#pragma unroll
    for (int s = 0; s < 8; s++) {
        const int chunk = tid + s * 128;
        const int row = chunk >> 4, c8 = (chunk & 15) << 3;
        const u32 sw = tile_off(row, c8);
        float v[8];
        const int gr = R0 + row;
        if (gr < n) {
            const float id = invd_s[row];
            float4 h0 = *(const float4*)(g_h   + (size_t)gr * DIM + c8);
            float4 h1 = *(const float4*)(g_h   + (size_t)gr * DIM + c8 + 4);
            float4 g0 = *(const float4*)(g_agg + (size_t)gr * DIM + c8);
            float4 g1 = *(const float4*)(g_agg + (size_t)gr * DIM + c8 + 4);
            v[0]=fmaf(g0.x,id,h0.x); v[1]=fmaf(g0.y,id,h0.y);
            v[2]=fmaf(g0.z,id,h0.z); v[3]=fmaf(g0.w,id,h0.w);
            v[4]=fmaf(g1.x,id,h1.x); v[5]=fmaf(g1.y,id,h1.y);
            v[6]=fmaf(g1.z,id,h1.z); v[7]=fmaf(g1.w,id,h1.w);
        } else {
#pragma unroll
            for (int j = 0; j < 8; j++) v[j] = 0.f;
        }
        split_store(sm, OFF_AH, OFF_AL, sw, v);
    }
#pragma unroll
    for (int s = 0; s < 16; s++) {
        const int chunk = tid + s * 128;
        const int row = chunk >> 4, c8 = (chunk & 15) << 3;
        const u32 sw = tile_off(row, c8);
        float w[8];
        float4 w0 = *(const float4*)(W1 + row * DIM + c8);
        float4 w1 = *(const float4*)(W1 + row * DIM + c8 + 4);
        w[0]=w0.x; w[1]=w0.y; w[2]=w0.z; w[3]=w0.w;
        w[4]=w1.x; w[5]=w1.y; w[6]=w1.z; w[7]=w1.w;
        split_store(sm, OFF_BH, OFF_BL, sw, w);
    }
    __syncthreads();

    float acc[16][4];
#pragma unroll
    for (int j = 0; j < 16; j++)
#pragma unroll
        for (int q = 0; q < 4; q++) acc[j][q] = 0.f;

    mma_mainloop(acc, sb, wid, lane);

    // epilogue: bias + relu + classifier partials
    const int r0 = R0 + wid * 16 + (lane >> 2), r1 = r0 + 8;
    const float* bp  = (const float*)(sm + OFF_BIAS);
    const float* wcs = (const float*)(sm + OFF_WC);
    float p0[4] = {0.f, 0.f, 0.f, 0.f};
    float p1[4] = {0.f, 0.f, 0.f, 0.f};
#pragma unroll
    for (int j = 0; j < 16; j++) {
        const int col = j * 8 + (lane & 3) * 2;
        const float2 bb = *(const float2*)(bp + col);
        const float ha = fmaxf(acc[j][0] + bb.x, 0.f);
        const float hb = fmaxf(acc[j][1] + bb.y, 0.f);
        const float hc = fmaxf(acc[j][2] + bb.x, 0.f);
        const float hd = fmaxf(acc[j][3] + bb.y, 0.f);
#pragma unroll
        for (int c = 0; c < 4; c++) {
            const float2 w = *(const float2*)(wcs + c * 128 + col);
            p0[c] = fmaf(ha, w.x, fmaf(hb, w.y, p0[c]));
            p1[c] = fmaf(hc, w.x, fmaf(hd, w.y, p1[c]));
        }
    }
    // reduce over the 4 lanes sharing a row
#pragma unroll
    for (int d = 1; d < 4; d <<= 1)
#pragma unroll
        for (int c = 0; c < 4; c++) {
            p0[c] += __shfl_xor_sync(0xffffffffu, p0[c], d);
            p1[c] += __shfl_xor_sync(0xffffffffu, p1[c], d);
        }

    if ((lane & 3) == 0) {
        const float* bcp = (const float*)(sm + OFF_BC);
        if (r0 < n)
            *(float4*)(out + (size_t)r0 * 4) =
                make_float4(p0[0] + bcp[0], p0[1] + bcp[1],
                            p0[2] + bcp[2], p0[3] + bcp[3]);
        if (r1 < n)
            *(float4*)(out + (size_t)r1 * 4) =
                make_float4(p1[0] + bcp[0], p1[1] + bcp[1],
                            p1[2] + bcp[2], p1[3] + bcp[3]);
    }
}

// ---------------------------------------------------------------------------
extern "C" void kernel_launch(void* const* d_in, const int* in_sizes, int n_in,
                              void* d_out, int out_size)
{
    const float* x  = (const float*)d_in[0];
    const int*   ei = (const int*)  d_in[1];
    const float* W0 = (const float*)d_in[2];
    const float* b0 = (const float*)d_in[3];
    const float* W1 = (const float*)d_in[4];
    const float* b1 = (const float*)d_in[5];
    const float* Wc = (const float*)d_in[6];
    const float* bc = (const float*)d_in[7];
    float* out = (float*)d_out;

    const int n       = in_sizes[0] / DIM;
    const int n_edges = in_sizes[1] / 2;

    void *aggp, *degp, *hp;
    cudaGetSymbolAddress(&aggp, g_agg);
    cudaGetSymbolAddress(&degp, g_deg);
    cudaGetSymbolAddress(&hp,   g_h);

    cudaFuncSetAttribute(gemm0_mma, cudaFuncAttributeMaxDynamicSharedMemorySize, SMEM_BYTES);
    cudaFuncSetAttribute(gemm1_mma, cudaFuncAttributeMaxDynamicSharedMemorySize, SMEM_BYTES);

    cudaMemsetAsync(aggp, 0, (size_t)n * DIM * sizeof(float));
    cudaMemsetAsync(degp, 0, (size_t)n * sizeof(float));

    const int gblocks = (n + 63) / 64;
    gemm0_mma<<<gblocks, 128, SMEM_BYTES>>>(x, W0, b0, (float*)hp, n);
    scatter_kernel<<<(n_edges + 7) / 8, 256>>>(ei, n_edges);
    gemm1_mma<<<gblocks, 128, SMEM_BYTES>>>(W1, b1, Wc, bc, out, n);
}